// round 1
// baseline (speedup 1.0000x reference)
#include <cuda_runtime.h>
#include <math.h>

#define NMAX 100000
#define EMAX 1600000
#define FIN  128
#define HID  64

// ---------------- scratch (device globals: no allocation allowed) ----------
__device__ float g_buf1[(size_t)NMAX * HID];  // scaled h1, later scaled h2
__device__ float g_buf2[(size_t)NMAX * HID];  // agg1 output (GEMM2 input)
__device__ float g_dinv[NMAX];
__device__ int   g_cnt[NMAX];
__device__ int   g_fill[NMAX];
__device__ int   g_rowstart[NMAX];
__device__ int   g_bsums[256];
__device__ int   g_csr[EMAX];

// ---------------- CSR build ------------------------------------------------
__global__ void k_zero(int n) {
    int i = blockIdx.x * blockDim.x + threadIdx.x;
    if (i < n) { g_cnt[i] = 0; g_fill[i] = 0; }
}

__global__ void k_hist(const int* __restrict__ dst, int e) {
    int i = blockIdx.x * blockDim.x + threadIdx.x;
    if (i < e) atomicAdd(&g_cnt[dst[i]], 1);
}

// block-level exclusive scan of g_cnt into g_rowstart (partial), block sums to g_bsums
__global__ void k_scanA(int n) {
    __shared__ int sm[512];
    int t = threadIdx.x;
    int i = blockIdx.x * 512 + t;
    int v = (i < n) ? g_cnt[i] : 0;
    sm[t] = v;
    __syncthreads();
#pragma unroll
    for (int off = 1; off < 512; off <<= 1) {
        int add = (t >= off) ? sm[t - off] : 0;
        __syncthreads();
        sm[t] += add;
        __syncthreads();
    }
    if (i < n) g_rowstart[i] = sm[t] - v;   // exclusive within block
    if (t == 511) g_bsums[blockIdx.x] = sm[511];
}

__global__ void k_scanB(int nb) {
    __shared__ int sm[256];
    int t = threadIdx.x;
    int v = (t < nb) ? g_bsums[t] : 0;
    sm[t] = v;
    __syncthreads();
#pragma unroll
    for (int off = 1; off < 256; off <<= 1) {
        int add = (t >= off) ? sm[t - off] : 0;
        __syncthreads();
        sm[t] += add;
        __syncthreads();
    }
    if (t < nb) g_bsums[t] = sm[t] - v;     // exclusive
}

__global__ void k_scanC(int n) {
    int i = blockIdx.x * blockDim.x + threadIdx.x;
    if (i < n) {
        g_rowstart[i] += g_bsums[i >> 9];
        g_dinv[i] = rsqrtf((float)g_cnt[i] + 1.0f);   // +1 = self-loop
    }
}

__global__ void k_scatter(const int* __restrict__ src, const int* __restrict__ dst, int e) {
    int i = blockIdx.x * blockDim.x + threadIdx.x;
    if (i < e) {
        int d = dst[i];
        int pos = g_rowstart[d] + atomicAdd(&g_fill[d], 1);
        g_csr[pos] = src[i];
    }
}

// ---------------- GEMM: out[r,:] = dinv[r] * (A[r,:] @ W)  ([n,K] @ [K,64]) -
template <int K>
__global__ __launch_bounds__(256) void gemm_kernel(
    const float* __restrict__ A, const float* __restrict__ W,
    const float* __restrict__ dinv, float* __restrict__ out, int n)
{
    constexpr int BM = 128;
    constexpr int BN = 64;
    constexpr int KC = 32;
    __shared__ float As[KC][BM + 1];   // +1 pad: conflict-free transposed stores
    __shared__ float Ws[KC][BN];

    const int tid = threadIdx.x;
    const int tx = tid & 15;   // 16 col-groups * 4 cols
    const int ty = tid >> 4;   // 16 row-groups * 8 rows
    const int blockRow = blockIdx.x * BM;

    float acc[8][4];
#pragma unroll
    for (int i = 0; i < 8; i++)
#pragma unroll
        for (int j = 0; j < 4; j++) acc[i][j] = 0.f;

    for (int kc = 0; kc < K; kc += KC) {
        // A tile: 128 rows x 32 k, coalesced float4 loads, transposed store
#pragma unroll
        for (int i = 0; i < 4; i++) {
            int m = (tid >> 3) + i * 32;
            int row = blockRow + m;
            int k = (tid & 7) * 4;
            float4 v = make_float4(0.f, 0.f, 0.f, 0.f);
            if (row < n) v = *(const float4*)(A + (size_t)row * K + kc + k);
            As[k + 0][m] = v.x;
            As[k + 1][m] = v.y;
            As[k + 2][m] = v.z;
            As[k + 3][m] = v.w;
        }
        // W tile: 32 k x 64 cols
#pragma unroll
        for (int i = 0; i < 2; i++) {
            int k = (tid >> 4) + i * 16;
            int c = (tid & 15) * 4;
            *(float4*)&Ws[k][c] = *(const float4*)(W + (size_t)(kc + k) * BN + c);
        }
        __syncthreads();

#pragma unroll
        for (int kk = 0; kk < KC; kk++) {
            float4 b4 = *(const float4*)&Ws[kk][tx * 4];
            float a[8];
#pragma unroll
            for (int i = 0; i < 8; i++) a[i] = As[kk][ty * 8 + i];
#pragma unroll
            for (int i = 0; i < 8; i++) {
                acc[i][0] = fmaf(a[i], b4.x, acc[i][0]);
                acc[i][1] = fmaf(a[i], b4.y, acc[i][1]);
                acc[i][2] = fmaf(a[i], b4.z, acc[i][2]);
                acc[i][3] = fmaf(a[i], b4.w, acc[i][3]);
            }
        }
        __syncthreads();
    }

#pragma unroll
    for (int i = 0; i < 8; i++) {
        int row = blockRow + ty * 8 + i;
        if (row < n) {
            float s = dinv[row];
            float4 v = make_float4(acc[i][0] * s, acc[i][1] * s, acc[i][2] * s, acc[i][3] * s);
            *(float4*)(out + (size_t)row * BN + tx * 4) = v;
        }
    }
}

// ---------------- aggregation: one warp per node ---------------------------
// acc = g[d] (self-loop, pre-scaled by dinv[src]=dinv[d]) + sum_{s in CSR(d)} g[s]
// v = relu(dinv[d]*acc + bias);  FINAL: out[d] = v . Wc + bc ; else out row = v
template <bool FINAL>
__global__ __launch_bounds__(256) void agg_kernel(
    const float* __restrict__ g, const float* __restrict__ bias,
    const float* __restrict__ Wc, const float* __restrict__ bc,
    float* __restrict__ out, int n)
{
    int w = (int)((blockIdx.x * blockDim.x + threadIdx.x) >> 5);
    int l = threadIdx.x & 31;
    if (w >= n) return;

    const float* gd = g + (size_t)w * HID;
    float acc0 = gd[l];
    float acc1 = gd[l + 32];

    int beg = g_rowstart[w];
    int end = beg + g_cnt[w];
    int j = beg;
    // 4-deep pipeline for MLP into L2
    for (; j + 4 <= end; j += 4) {
        int s0 = __ldg(&g_csr[j + 0]);
        int s1 = __ldg(&g_csr[j + 1]);
        int s2 = __ldg(&g_csr[j + 2]);
        int s3 = __ldg(&g_csr[j + 3]);
        const float* p0 = g + (size_t)s0 * HID;
        const float* p1 = g + (size_t)s1 * HID;
        const float* p2 = g + (size_t)s2 * HID;
        const float* p3 = g + (size_t)s3 * HID;
        float a0 = p0[l], c0 = p0[l + 32];
        float a1 = p1[l], c1 = p1[l + 32];
        float a2 = p2[l], c2 = p2[l + 32];
        float a3 = p3[l], c3 = p3[l + 32];
        acc0 += (a0 + a1) + (a2 + a3);
        acc1 += (c0 + c1) + (c2 + c3);
    }
    for (; j < end; ++j) {
        const float* p = g + (size_t)__ldg(&g_csr[j]) * HID;
        acc0 += p[l];
        acc1 += p[l + 32];
    }

    float dv = g_dinv[w];
    float v0 = fmaxf(fmaf(dv, acc0, bias[l]), 0.f);
    float v1 = fmaxf(fmaf(dv, acc1, bias[l + 32]), 0.f);

    if (FINAL) {
        float p = fmaf(v0, Wc[l], v1 * Wc[l + 32]);
#pragma unroll
        for (int off = 16; off; off >>= 1) p += __shfl_xor_sync(0xffffffffu, p, off);
        if (l == 0) out[w] = p + bc[0];
    } else {
        out[(size_t)w * HID + l] = v0;
        out[(size_t)w * HID + l + 32] = v1;
    }
}

// ---------------- launch ----------------------------------------------------
extern "C" void kernel_launch(void* const* d_in, const int* in_sizes, int n_in,
                              void* d_out, int out_size)
{
    const float* x  = (const float*)d_in[0];
    const int*   ei = (const int*)d_in[1];
    const float* W1 = (const float*)d_in[2];
    const float* b1 = (const float*)d_in[3];
    const float* W2 = (const float*)d_in[4];
    const float* b2 = (const float*)d_in[5];
    const float* Wc = (const float*)d_in[6];
    const float* bc = (const float*)d_in[7];
    float* out = (float*)d_out;

    const int n = in_sizes[0] / FIN;
    const int e = in_sizes[1] / 2;
    const int* src = ei;
    const int* dst = ei + e;

    void* p1; void* p2;
    cudaGetSymbolAddress(&p1, g_buf1);
    cudaGetSymbolAddress(&p2, g_buf2);
    float* buf1 = (float*)p1;
    float* buf2 = (float*)p2;
    void* pd; cudaGetSymbolAddress(&pd, g_dinv);
    float* dinv = (float*)pd;

    const int nb_n = (n + 255) / 256;
    const int nb_e = (e + 255) / 256;
    const int nb_scan = (n + 511) / 512;

    // CSR build (+ degrees incl. self-loop)
    k_zero<<<nb_n, 256>>>(n);
    k_hist<<<nb_e, 256>>>(dst, e);
    k_scanA<<<nb_scan, 512>>>(n);
    k_scanB<<<1, 256>>>(nb_scan);
    k_scanC<<<nb_n, 256>>>(n);
    k_scatter<<<nb_e, 256>>>(src, dst, e);

    // layer 1: g1 = dinv * (x @ W1); agg1 = relu(dinv*(sum g1) + b1)
    gemm_kernel<FIN><<<(n + 127) / 128, 256>>>(x, W1, dinv, buf1, n);
    agg_kernel<false><<<(n * 32 + 255) / 256, 256>>>(buf1, b1, Wc, bc, buf2, n);

    // layer 2: g2 = dinv * (agg1 @ W2); out = relu(dinv*(sum g2) + b2) . Wc + bc
    gemm_kernel<HID><<<(n + 127) / 128, 256>>>(buf2, W2, dinv, buf1, n);
    agg_kernel<true><<<(n * 32 + 255) / 256, 256>>>(buf1, b2, Wc, bc, out, n);
}

// round 2
// speedup vs baseline: 1.1320x; 1.1320x over previous
#include <cuda_runtime.h>
#include <cuda_fp16.h>
#include <math.h>

#define NMAX 100000
#define EMAX 1600000
#define FIN  128
#define HID  64

// ---------------- scratch (device globals: no allocation allowed) ----------
__device__ __half2 g_gh [NMAX * 32];   // gather buffer: dinv-prescaled GEMM out
__device__ __half2 g_ahi[NMAX * 32];   // agg1 output, hi f16 plane (GEMM2 A)
__device__ __half2 g_alo[NMAX * 32];   // agg1 output, lo f16 plane
__device__ float   g_dinv[NMAX];
__device__ int     g_cnt[NMAX];
__device__ int     g_fill[NMAX];
__device__ int     g_rowstart[NMAX];
__device__ int     g_csr[EMAX];
__device__ int     g_total;

// ---------------- helpers ---------------------------------------------------
__device__ __forceinline__ unsigned h2u(__half2 h) {
    return *reinterpret_cast<unsigned*>(&h);
}
// split (x,y) fp32 pair into hi/lo f16x2 planes: x ~= hi + lo to ~22 mantissa bits
__device__ __forceinline__ void split2(float x, float y, unsigned& hi, unsigned& lo) {
    __half2 h = __floats2half2_rn(x, y);
    float2 hf = __half22float2(h);
    __half2 l = __floats2half2_rn(x - hf.x, y - hf.y);
    hi = h2u(h); lo = h2u(l);
}

#define MMA16816(c, a0, a1, a2, a3, b0, b1)                                      \
    asm volatile("mma.sync.aligned.m16n8k16.row.col.f32.f16.f16.f32 "            \
                 "{%0,%1,%2,%3},{%4,%5,%6,%7},{%8,%9},{%0,%1,%2,%3};"            \
                 : "+f"(c[0]), "+f"(c[1]), "+f"(c[2]), "+f"(c[3])                \
                 : "r"(a0), "r"(a1), "r"(a2), "r"(a3), "r"(b0), "r"(b1))

// ---------------- CSR build ------------------------------------------------
__global__ void k_init(int n) {
    int i = blockIdx.x * blockDim.x + threadIdx.x;
    if (i < n) { g_cnt[i] = 0; g_fill[i] = 0; }
    if (i == 0) g_total = 0;
}

__global__ void k_hist(const int* __restrict__ dst, int e) {
    int i = blockIdx.x * blockDim.x + threadIdx.x;
    if (i < e) atomicAdd(&g_cnt[dst[i]], 1);
}

// warp-aggregated offset assignment (replaces 3-kernel scan)
__global__ void k_offsets(int n) {
    int i = blockIdx.x * blockDim.x + threadIdx.x;
    int lane = threadIdx.x & 31;
    int c = (i < n) ? g_cnt[i] : 0;
    int pre = c;
#pragma unroll
    for (int off = 1; off < 32; off <<= 1) {
        int t = __shfl_up_sync(0xffffffffu, pre, off);
        if (lane >= off) pre += t;
    }
    int tot = __shfl_sync(0xffffffffu, pre, 31);
    int base = 0;
    if (lane == 31) base = atomicAdd(&g_total, tot);
    base = __shfl_sync(0xffffffffu, base, 31);
    if (i < n) {
        g_rowstart[i] = base + pre - c;
        g_dinv[i] = rsqrtf((float)c + 1.0f);   // +1 = self-loop
    }
}

__global__ void k_scatter(const int* __restrict__ src, const int* __restrict__ dst, int e) {
    int i = blockIdx.x * blockDim.x + threadIdx.x;
    if (i < e) {
        int d = dst[i];
        int pos = g_rowstart[d] + atomicAdd(&g_fill[d], 1);
        g_csr[pos] = src[i];
    }
}

// ---------------- tensor-core GEMM (f16-split, fp32-accurate) --------------
// out = dinv[row] * (A[row,:] @ W)  -> g_gh as half2, [n x 64]
// AH2=false: A fp32 [n x K].  AH2=true: A from g_ahi/g_alo half2 planes [n x 32].
template <int K, bool AH2>
__global__ __launch_bounds__(256) void gemm_kernel(
    const float* __restrict__ A, const float* __restrict__ W, int n)
{
    __shared__ unsigned As2[2][128][20];   // [plane][row][k2], pad 20 = conflict-free frags
    __shared__ unsigned Ws2[2][64][20];    // [plane][n][k2]

    const int tid = threadIdx.x;
    const int wid = tid >> 5, lane = tid & 31;
    const int g = lane >> 2, t = lane & 3;
    const int blockRow = blockIdx.x * 128;
    const int wr = wid * 16;

    float c[8][4];
#pragma unroll
    for (int i = 0; i < 8; i++)
#pragma unroll
        for (int j = 0; j < 4; j++) c[i][j] = 0.f;

    for (int kc = 0; kc < K; kc += 32) {
        // ---- W tile: [32 k x 64 n] -> Ws2[n][k2] (pairs along k), split hi/lo
        {
            int nn = tid & 63;
            int k2b = (tid >> 6) * 4;
#pragma unroll
            for (int j = 0; j < 4; j++) {
                int k2 = k2b + j;
                float w0 = W[(size_t)(kc + 2 * k2) * 64 + nn];
                float w1 = W[(size_t)(kc + 2 * k2 + 1) * 64 + nn];
                unsigned hi, lo; split2(w0, w1, hi, lo);
                Ws2[0][nn][k2] = hi; Ws2[1][nn][k2] = lo;
            }
        }
        // ---- A tile: 128 rows x 32 k
        if (AH2) {
#pragma unroll
            for (int j = 0; j < 8; j++) {
                int idx = tid + j * 256;           // 0..2047
                int row = idx >> 4, k2 = idx & 15;
                int grow = blockRow + row;
                unsigned vh = 0, vl = 0;
                if (grow < n) {
                    int off = grow * 32 + (kc >> 1) + k2;
                    vh = reinterpret_cast<const unsigned*>(g_ahi)[off];
                    vl = reinterpret_cast<const unsigned*>(g_alo)[off];
                }
                As2[0][row][k2] = vh; As2[1][row][k2] = vl;
            }
        } else {
            int row = tid >> 1;
            int kh = (tid & 1) * 16;
            int grow = blockRow + row;
#pragma unroll
            for (int j = 0; j < 4; j++) {
                float4 v = make_float4(0.f, 0.f, 0.f, 0.f);
                if (grow < n)
                    v = *reinterpret_cast<const float4*>(A + (size_t)grow * K + kc + kh + j * 4);
                unsigned h0, l0, h1, l1;
                split2(v.x, v.y, h0, l0);
                split2(v.z, v.w, h1, l1);
                int k2 = (kh >> 1) + j * 2;
                As2[0][row][k2] = h0; As2[0][row][k2 + 1] = h1;
                As2[1][row][k2] = l0; As2[1][row][k2 + 1] = l1;
            }
        }
        __syncthreads();

        // ---- compute: 2 k-steps of 16
#pragma unroll
        for (int ks = 0; ks < 2; ks++) {
            const int kb = ks * 8;
            unsigned a0h = As2[0][wr + g][t + kb],     a1h = As2[0][wr + g + 8][t + kb];
            unsigned a2h = As2[0][wr + g][t + 4 + kb], a3h = As2[0][wr + g + 8][t + 4 + kb];
            unsigned a0l = As2[1][wr + g][t + kb],     a1l = As2[1][wr + g + 8][t + kb];
            unsigned a2l = As2[1][wr + g][t + 4 + kb], a3l = As2[1][wr + g + 8][t + 4 + kb];
#pragma unroll
            for (int nt = 0; nt < 8; nt++) {
                unsigned b0h = Ws2[0][nt * 8 + g][t + kb], b1h = Ws2[0][nt * 8 + g][t + 4 + kb];
                unsigned b0l = Ws2[1][nt * 8 + g][t + kb], b1l = Ws2[1][nt * 8 + g][t + 4 + kb];
                MMA16816(c[nt], a0h, a1h, a2h, a3h, b0h, b1h);   // hi*hi
                MMA16816(c[nt], a0l, a1l, a2l, a3l, b0h, b1h);   // lo*hi
                MMA16816(c[nt], a0h, a1h, a2h, a3h, b0l, b1l);   // hi*lo
            }
        }
        __syncthreads();
    }

    // ---- epilogue: scale by dinv, pack half2 into gather buffer
    int r0 = blockRow + wr + g, r1 = r0 + 8;
    float dv0 = (r0 < n) ? g_dinv[r0] : 0.f;
    float dv1 = (r1 < n) ? g_dinv[r1] : 0.f;
#pragma unroll
    for (int nt = 0; nt < 8; nt++) {
        if (r0 < n) g_gh[r0 * 32 + nt * 4 + t] = __floats2half2_rn(c[nt][0] * dv0, c[nt][1] * dv0);
        if (r1 < n) g_gh[r1 * 32 + nt * 4 + t] = __floats2half2_rn(c[nt][2] * dv1, c[nt][3] * dv1);
    }
}

// ---------------- aggregation: one warp per node, half2 gathers ------------
// acc = gh[d] (self-loop) + sum_{s in CSR(d)} gh[s];  v = relu(dinv[d]*acc + b)
// FINAL: out[d] = v . Wc + bc;  else: write hi/lo f16 planes for GEMM2
template <bool FINAL>
__global__ __launch_bounds__(256) void agg_kernel(
    const float* __restrict__ bias, const float* __restrict__ Wc,
    const float* __restrict__ bc, float* __restrict__ out, int n)
{
    int w = (int)((blockIdx.x * 256 + threadIdx.x) >> 5);
    int l = threadIdx.x & 31;
    if (w >= n) return;

    float2 acc = __half22float2(g_gh[w * 32 + l]);

    int beg = g_rowstart[w];
    int m = g_cnt[w];
    for (int base = 0; base < m; base += 32) {
        int rem = m - base; if (rem > 32) rem = 32;
        int myidx = (l < rem) ? g_csr[beg + base + l] : 0;
        int j = 0;
        for (; j + 4 <= rem; j += 4) {
            int s0 = __shfl_sync(0xffffffffu, myidx, j);
            int s1 = __shfl_sync(0xffffffffu, myidx, j + 1);
            int s2 = __shfl_sync(0xffffffffu, myidx, j + 2);
            int s3 = __shfl_sync(0xffffffffu, myidx, j + 3);
            float2 f0 = __half22float2(g_gh[s0 * 32 + l]);
            float2 f1 = __half22float2(g_gh[s1 * 32 + l]);
            float2 f2 = __half22float2(g_gh[s2 * 32 + l]);
            float2 f3 = __half22float2(g_gh[s3 * 32 + l]);
            acc.x += (f0.x + f1.x) + (f2.x + f3.x);
            acc.y += (f0.y + f1.y) + (f2.y + f3.y);
        }
        for (; j < rem; j++) {
            int s = __shfl_sync(0xffffffffu, myidx, j);
            float2 f = __half22float2(g_gh[s * 32 + l]);
            acc.x += f.x; acc.y += f.y;
        }
    }

    float dv = g_dinv[w];
    float2 b = reinterpret_cast<const float2*>(bias)[l];
    float v0 = fmaxf(fmaf(dv, acc.x, b.x), 0.f);
    float v1 = fmaxf(fmaf(dv, acc.y, b.y), 0.f);

    if (FINAL) {
        float2 wc = reinterpret_cast<const float2*>(Wc)[l];
        float p = fmaf(v0, wc.x, v1 * wc.y);
#pragma unroll
        for (int off = 16; off; off >>= 1) p += __shfl_xor_sync(0xffffffffu, p, off);
        if (l == 0) out[w] = p + bc[0];
    } else {
        unsigned hi, lo; split2(v0, v1, hi, lo);
        reinterpret_cast<unsigned*>(g_ahi)[w * 32 + l] = hi;
        reinterpret_cast<unsigned*>(g_alo)[w * 32 + l] = lo;
    }
}

// ---------------- launch ----------------------------------------------------
extern "C" void kernel_launch(void* const* d_in, const int* in_sizes, int n_in,
                              void* d_out, int out_size)
{
    const float* x  = (const float*)d_in[0];
    const int*   ei = (const int*)d_in[1];
    const float* W1 = (const float*)d_in[2];
    const float* b1 = (const float*)d_in[3];
    const float* W2 = (const float*)d_in[4];
    const float* b2 = (const float*)d_in[5];
    const float* Wc = (const float*)d_in[6];
    const float* bc = (const float*)d_in[7];
    float* out = (float*)d_out;

    const int n = in_sizes[0] / FIN;
    const int e = in_sizes[1] / 2;
    const int* src = ei;
    const int* dst = ei + e;

    const int nbn = (n + 255) / 256;
    const int nbe = (e + 255) / 256;

    // CSR build (+ degrees incl. self-loop)
    k_init<<<nbn, 256>>>(n);
    k_hist<<<nbe, 256>>>(dst, e);
    k_offsets<<<nbn, 256>>>(n);
    k_scatter<<<nbe, 256>>>(src, dst, e);

    // layer 1: gh = dinv * (x @ W1); agg1 = relu(dinv*sum + b1) -> f16 split planes
    gemm_kernel<FIN, false><<<(n + 127) / 128, 256>>>(x, W1, n);
    agg_kernel<false><<<(n + 7) / 8, 256>>>(b1, nullptr, nullptr, nullptr, n);

    // layer 2: gh = dinv * (agg1 @ W2); out = relu(dinv*sum + b2) . Wc + bc
    gemm_kernel<HID, true><<<(n + 127) / 128, 256>>>(nullptr, W2, n);
    agg_kernel<true><<<(n + 7) / 8, 256>>>(b2, Wc, bc, out, n);
}